// round 2
// baseline (speedup 1.0000x reference)
#include <cuda_runtime.h>
#include <math.h>

// ---------------------------------------------------------------------------
// DiagonalElman: output = (cell_out) @ W_out^T,  cell_out from tanh recurrence
//   x_proj = x @ W_in^T           [B,T,D]
//   xw     = x_proj @ W_x^T       [B,T,D]
//   h_t    = tanh(xw_t + alpha*h_{t-1} + b);  out_t = h_t * silu(x_proj_t + b_gate)
//   output = cell_out @ W_out^T   [B,T,D];  h_final appended at d_out + B*T*D
// B=8, T=2048, D=1024 (derived from in_sizes at runtime).
// ---------------------------------------------------------------------------

#define MAX_BTD (8 * 2048 * 1024)

// scratch (static device globals: no allocation inside kernel_launch)
__device__ float g_xproj[MAX_BTD];
__device__ float g_xw[MAX_BTD];   // cell_out overwrites this in-place

// ---------------------------------------------------------------------------
// SGEMM (NT): C[M,N] = A[M,K] * B[N,K]^T, all row-major, fp32.
// 128x128 block tile, BK=16, 256 threads, 8x8 per-thread micro-tile.
// Assumes M%128==0, N%128==0, K%16==0 (true here: 16384/1024/1024).
// ---------------------------------------------------------------------------
#define BM 128
#define BN 128
#define BKT 16
#define TM 8
#define TN 8

__global__ __launch_bounds__(256, 1) void sgemm_nt(
    const float* __restrict__ A, const float* __restrict__ Bmat,
    float* __restrict__ C, int M, int N, int K)
{
    __shared__ float As[BKT][BM];
    __shared__ float Bs[BKT][BN];

    const int tid = threadIdx.x;
    const int m0 = blockIdx.y * BM;
    const int n0 = blockIdx.x * BN;

    // load layout: each thread loads 2 float4 from A and 2 from B
    const int lr = tid >> 2;         // 0..63
    const int lc = (tid & 3) << 2;   // 0,4,8,12

    const int tx = tid & 15;         // 0..15 (n direction)
    const int ty = tid >> 4;         // 0..15 (m direction)

    float acc[TM][TN];
    #pragma unroll
    for (int i = 0; i < TM; i++)
        #pragma unroll
        for (int j = 0; j < TN; j++) acc[i][j] = 0.f;

    const float* Ab = A + (size_t)m0 * K;
    const float* Bb = Bmat + (size_t)n0 * K;

    for (int k0 = 0; k0 < K; k0 += BKT) {
        #pragma unroll
        for (int r = 0; r < 2; r++) {
            int row = lr + r * 64;
            float4 v = *(const float4*)(Ab + (size_t)row * K + k0 + lc);
            As[lc + 0][row] = v.x;
            As[lc + 1][row] = v.y;
            As[lc + 2][row] = v.z;
            As[lc + 3][row] = v.w;
        }
        #pragma unroll
        for (int r = 0; r < 2; r++) {
            int row = lr + r * 64;
            float4 v = *(const float4*)(Bb + (size_t)row * K + k0 + lc);
            Bs[lc + 0][row] = v.x;
            Bs[lc + 1][row] = v.y;
            Bs[lc + 2][row] = v.z;
            Bs[lc + 3][row] = v.w;
        }
        __syncthreads();

        #pragma unroll
        for (int k = 0; k < BKT; k++) {
            float ra[TM], rb[TN];
            #pragma unroll
            for (int i = 0; i < TM; i += 4) {
                float4 v = *(const float4*)(&As[k][ty * TM + i]);
                ra[i] = v.x; ra[i+1] = v.y; ra[i+2] = v.z; ra[i+3] = v.w;
            }
            #pragma unroll
            for (int j = 0; j < TN; j += 4) {
                float4 v = *(const float4*)(&Bs[k][tx * TN + j]);
                rb[j] = v.x; rb[j+1] = v.y; rb[j+2] = v.z; rb[j+3] = v.w;
            }
            #pragma unroll
            for (int i = 0; i < TM; i++)
                #pragma unroll
                for (int j = 0; j < TN; j++)
                    acc[i][j] = fmaf(ra[i], rb[j], acc[i][j]);
        }
        __syncthreads();
    }

    #pragma unroll
    for (int i = 0; i < TM; i++) {
        size_t row = (size_t)(m0 + ty * TM + i);
        #pragma unroll
        for (int j = 0; j < TN; j += 4) {
            float4 v = make_float4(acc[i][j], acc[i][j+1], acc[i][j+2], acc[i][j+3]);
            *(float4*)(C + row * N + n0 + tx * TN + j) = v;
        }
    }
}

// ---------------------------------------------------------------------------
// Recurrence: one thread per (b, d) chain; T sequential steps.
// Reads g_xw (pre-activation input) and g_xproj (gate input).
// Writes cell_out in-place into g_xw, and h_final into hfin.
// ---------------------------------------------------------------------------
__device__ __forceinline__ float fast_tanh(float x) {
    float y;
    asm("tanh.approx.f32 %0, %1;" : "=f"(y) : "f"(x));
    return y;
}

__global__ __launch_bounds__(256) void recurrence_kernel(
    float* __restrict__ xw,            // [B,T,D] in, cell_out out (in-place)
    const float* __restrict__ xp,      // [B,T,D] gate input (x_proj)
    const float* __restrict__ h0,      // [B,D]
    const float* __restrict__ alpha_raw,
    const float* __restrict__ bias,
    const float* __restrict__ bgate,
    float* __restrict__ hfin,          // [B,D] (may be null)
    int B, int T, int D)
{
    int idx = blockIdx.x * blockDim.x + threadIdx.x;
    if (idx >= B * D) return;
    int bb = idx / D;
    int d  = idx - bb * D;

    float alpha = 1.f / (1.f + __expf(-alpha_raw[d]));
    float bv = bias[d];
    float bg = bgate[d];
    float h  = h0[idx];

    size_t base = (size_t)bb * T * D + d;
    #pragma unroll 4
    for (int t = 0; t < T; t++) {
        size_t off = base + (size_t)t * D;
        float xw_t = xw[off];
        float xr_t = xp[off];
        float pre  = fmaf(alpha, h, xw_t + bv);
        h = fast_tanh(pre);
        float g = xr_t + bg;
        float s = g * (1.f / (1.f + __expf(-g)));   // silu
        xw[off] = h * s;
    }
    if (hfin) hfin[idx] = h;
}

// ---------------------------------------------------------------------------
// Launch
// ---------------------------------------------------------------------------
extern "C" void kernel_launch(void* const* d_in, const int* in_sizes, int n_in,
                              void* d_out, int out_size)
{
    const float* x         = (const float*)d_in[0];
    const float* h0        = (const float*)d_in[1];
    const float* W_in      = (const float*)d_in[2];
    const float* W_x       = (const float*)d_in[3];
    const float* alpha_raw = (const float*)d_in[4];
    const float* b         = (const float*)d_in[5];
    const float* b_gate    = (const float*)d_in[6];
    const float* W_out     = (const float*)d_in[7];
    float* out = (float*)d_out;

    const int D   = in_sizes[4];          // 1024
    const int BD  = in_sizes[1];          // B*D
    const int Bn  = BD / D;               // 8
    const int BTD = in_sizes[0];          // B*T*D
    const int T   = BTD / BD;             // 2048
    const int M   = Bn * T;               // 16384

    float *xproj, *xw;
    cudaGetSymbolAddress((void**)&xproj, g_xproj);
    cudaGetSymbolAddress((void**)&xw, g_xw);

    dim3 blk(256);
    dim3 grid(D / BN, M / BM);

    // 1) x_proj = x @ W_in^T
    sgemm_nt<<<grid, blk>>>(x, W_in, xproj, M, D, D);
    // 2) xw = x_proj @ W_x^T
    sgemm_nt<<<grid, blk>>>(xproj, W_x, xw, M, D, D);

    // 3) recurrence (writes cell_out into xw in-place, h_final into tail of out)
    float* hfin = (out_size >= BTD + BD) ? (out + BTD) : nullptr;
    int nthreads = Bn * D;
    recurrence_kernel<<<(nthreads + 255) / 256, 256>>>(
        xw, xproj, h0, alpha_raw, b, b_gate, hfin, Bn, T, D);

    // 4) output = cell_out @ W_out^T
    sgemm_nt<<<grid, blk>>>(xw, W_out, out, M, D, D);
}

// round 4
// speedup vs baseline: 2.7087x; 2.7087x over previous
#include <cuda_runtime.h>
#include <cuda_bf16.h>
#include <stdint.h>

// ---------------------------------------------------------------------------
// DiagonalElman on GB300 (base sm_103 ISA: mma.sync bf16 + ldmatrix + cp.async)
//   x_proj = x @ W_in^T ; xw = x_proj @ W_x^T
//   h_t = tanh(xw_t + alpha*h_{t-1} + b); out_t = h_t * silu(x_proj_t + b_gate)
//   output = cell_out @ W_out^T ; h_final appended at d_out + B*T*D
// GEMMs: bf16 3-term split (Ah*Bh + Ah*Bl + Al*Bh), fp32 accum (HMMA).
// ---------------------------------------------------------------------------

#define MAX_BTD (8 * 2048 * 1024)
#define MAX_DD  (1024 * 1024)

__device__ float g_xproj[MAX_BTD];            // fp32 x_proj (gate input)
__device__ float g_xw[MAX_BTD];               // fp32 xw (recurrence input)
__device__ __nv_bfloat16 g_xh[MAX_BTD], g_xl[MAX_BTD];     // x split
__device__ __nv_bfloat16 g_xph[MAX_BTD], g_xpl[MAX_BTD];   // x_proj split
__device__ __nv_bfloat16 g_ch[MAX_BTD], g_cl[MAX_BTD];     // cell_out split
__device__ __nv_bfloat16 g_wih[MAX_DD], g_wil[MAX_DD];
__device__ __nv_bfloat16 g_wxh[MAX_DD], g_wxl[MAX_DD];
__device__ __nv_bfloat16 g_woh[MAX_DD], g_wol[MAX_DD];

// ============================ helpers =======================================
__device__ __forceinline__ uint32_t smem_u32(const void* p) {
    uint32_t a;
    asm("{ .reg .u64 t; cvta.to.shared.u64 t, %1; cvt.u32.u64 %0, t; }"
        : "=r"(a) : "l"(p));
    return a;
}
#define SWZ(x) ((x) ^ (((x) >> 3) & 0x70))

// split one float into truncated-hi bf16 bits and rounded residual-lo bf16
__device__ __forceinline__ void split1(float v, uint16_t& hi, uint16_t& lo) {
    uint32_t u = __float_as_uint(v);
    uint32_t hb = u & 0xFFFF0000u;
    hi = (uint16_t)(u >> 16);
    float r = v - __uint_as_float(hb);
    uint16_t lb;
    asm("cvt.rn.bf16.f32 %0, %1;" : "=h"(lb) : "f"(r));
    lo = lb;
}

// convert fp32 array -> hi/lo bf16 arrays (vectorized by 4)
__global__ __launch_bounds__(256) void split_kernel(
    const float* __restrict__ src, __nv_bfloat16* __restrict__ hi,
    __nv_bfloat16* __restrict__ lo, int n4) {
    int i = blockIdx.x * blockDim.x + threadIdx.x;
    if (i >= n4) return;
    float4 v = ((const float4*)src)[i];
    uint16_t h[4], l[4];
    split1(v.x, h[0], l[0]); split1(v.y, h[1], l[1]);
    split1(v.z, h[2], l[2]); split1(v.w, h[3], l[3]);
    uint64_t hp = (uint64_t)h[0] | ((uint64_t)h[1] << 16) | ((uint64_t)h[2] << 32) | ((uint64_t)h[3] << 48);
    uint64_t lp = (uint64_t)l[0] | ((uint64_t)l[1] << 16) | ((uint64_t)l[2] << 32) | ((uint64_t)l[3] << 48);
    ((uint64_t*)hi)[i] = hp;
    ((uint64_t*)lo)[i] = lp;
}

// ============================ GEMM ==========================================
// C[M,N] = A[M,K] * B[N,K]^T, fp32 accum from bf16 hi/lo splits.
// CTA tile 128x128, BK=64 (128B rows). 8 warps, each 64m x 32n.
#define BKB 128                 // bytes per smem row (64 bf16)
#define TILE_BYTES (128 * BKB)  // 16 KB per operand tile
#define STAGE_BYTES (4 * TILE_BYTES)  // Ah, Al, Bh, Bl
#define GSMEM (2 * STAGE_BYTES)       // 128 KB double buffered

__device__ __forceinline__ void cp16(uint32_t dst, const void* src) {
    asm volatile("cp.async.cg.shared.global [%0], [%1], 16;" :: "r"(dst), "l"(src));
}
__device__ __forceinline__ void ldsm4(uint32_t* r, uint32_t addr) {
    asm volatile("ldmatrix.sync.aligned.m8n8.x4.shared.b16 {%0,%1,%2,%3}, [%4];"
                 : "=r"(r[0]), "=r"(r[1]), "=r"(r[2]), "=r"(r[3]) : "r"(addr));
}
__device__ __forceinline__ void mma16816(float* c, const uint32_t* a, uint32_t b0, uint32_t b1) {
    asm volatile(
        "mma.sync.aligned.m16n8k16.row.col.f32.bf16.bf16.f32 "
        "{%0,%1,%2,%3}, {%4,%5,%6,%7}, {%8,%9}, {%0,%1,%2,%3};"
        : "+f"(c[0]), "+f"(c[1]), "+f"(c[2]), "+f"(c[3])
        : "r"(a[0]), "r"(a[1]), "r"(a[2]), "r"(a[3]), "r"(b0), "r"(b1));
}

// load one 128x64 bf16 tile into swizzled smem via cp.async
__device__ __forceinline__ void load_tile(uint32_t sbase, const __nv_bfloat16* gbase,
                                          int K, int tid) {
#pragma unroll
    for (int i = 0; i < 4; i++) {
        int u = tid + 256 * i;            // 0..1023
        int row = u >> 3;
        int c = u & 7;
        const __nv_bfloat16* src = gbase + (size_t)row * K + c * 8;
        uint32_t dst = sbase + SWZ((uint32_t)(row * BKB + c * 16));
        cp16(dst, src);
    }
}

__global__ __launch_bounds__(256, 1) void gemm_bf16x3(
    const __nv_bfloat16* __restrict__ Ah, const __nv_bfloat16* __restrict__ Al,
    const __nv_bfloat16* __restrict__ Bh, const __nv_bfloat16* __restrict__ Bl,
    float* __restrict__ C,
    __nv_bfloat16* __restrict__ Chi, __nv_bfloat16* __restrict__ Clo,
    int M, int N, int K) {
    extern __shared__ char sm[];
    const uint32_t sb = smem_u32(sm);

    const int tid = threadIdx.x;
    const int wid = tid >> 5;
    const int lane = tid & 31;
    const int m0 = blockIdx.y * 128;
    const int n0 = blockIdx.x * 128;
    const int wm = (wid & 1) * 64;     // warp m offset within tile
    const int wn = (wid >> 1) * 32;    // warp n offset within tile

    const __nv_bfloat16* gAh = Ah + (size_t)m0 * K;
    const __nv_bfloat16* gAl = Al + (size_t)m0 * K;
    const __nv_bfloat16* gBh = Bh + (size_t)n0 * K;
    const __nv_bfloat16* gBl = Bl + (size_t)n0 * K;

    float acc[4][4][4];
#pragma unroll
    for (int i = 0; i < 4; i++)
#pragma unroll
        for (int j = 0; j < 4; j++)
#pragma unroll
            for (int q = 0; q < 4; q++) acc[i][j][q] = 0.f;

    const int NC = K / 64;

    // prologue: stage 0
    {
        uint32_t s0 = sb;
        load_tile(s0, gAh, K, tid);
        load_tile(s0 + TILE_BYTES, gAl, K, tid);
        load_tile(s0 + 2 * TILE_BYTES, gBh, K, tid);
        load_tile(s0 + 3 * TILE_BYTES, gBl, K, tid);
        asm volatile("cp.async.commit_group;" ::: "memory");
    }

    // ldmatrix lane addressing (within a tile): row = base + (lane&15), colbyte = (lane>>4)*16
    const int lrow = lane & 15;
    const int lcol = (lane >> 4) * 16;

    for (int c = 0; c < NC; c++) {
        if (c + 1 < NC) {
            uint32_t s1 = sb + ((c + 1) & 1) * STAGE_BYTES;
            int k0 = (c + 1) * 64;
            load_tile(s1, gAh + k0, K, tid);
            load_tile(s1 + TILE_BYTES, gAl + k0, K, tid);
            load_tile(s1 + 2 * TILE_BYTES, gBh + k0, K, tid);
            load_tile(s1 + 3 * TILE_BYTES, gBl + k0, K, tid);
            asm volatile("cp.async.commit_group;" ::: "memory");
            asm volatile("cp.async.wait_group 1;" ::: "memory");
        } else {
            asm volatile("cp.async.wait_group 0;" ::: "memory");
        }
        __syncthreads();

        uint32_t st = sb + (c & 1) * STAGE_BYTES;
        uint32_t sAh = st, sAl = st + TILE_BYTES;
        uint32_t sBh = st + 2 * TILE_BYTES, sBl = st + 3 * TILE_BYTES;

#pragma unroll
        for (int ks = 0; ks < 4; ks++) {
            const int kb = ks * 32 + lcol;
            uint32_t ra[4][4], rbh[2][4], rbl[2][4];
            // A hi fragments (4 m16 tiles)
#pragma unroll
            for (int mi = 0; mi < 4; mi++) {
                int row = wm + mi * 16 + lrow;
                ldsm4(ra[mi], sAh + SWZ((uint32_t)(row * BKB + kb)));
            }
            // B hi fragments (2 n16 tiles)
#pragma unroll
            for (int bj = 0; bj < 2; bj++) {
                int row = wn + bj * 16 + lrow;
                ldsm4(rbh[bj], sBh + SWZ((uint32_t)(row * BKB + kb)));
                ldsm4(rbl[bj], sBl + SWZ((uint32_t)(row * BKB + kb)));
            }
            // term 1: Ah * Bh
#pragma unroll
            for (int mi = 0; mi < 4; mi++)
#pragma unroll
                for (int nj = 0; nj < 4; nj++) {
                    uint32_t b0 = (nj & 1) ? rbh[nj >> 1][1] : rbh[nj >> 1][0];
                    uint32_t b1 = (nj & 1) ? rbh[nj >> 1][3] : rbh[nj >> 1][2];
                    mma16816(acc[mi][nj], ra[mi], b0, b1);
                }
            // term 2: Ah * Bl
#pragma unroll
            for (int mi = 0; mi < 4; mi++)
#pragma unroll
                for (int nj = 0; nj < 4; nj++) {
                    uint32_t b0 = (nj & 1) ? rbl[nj >> 1][1] : rbl[nj >> 1][0];
                    uint32_t b1 = (nj & 1) ? rbl[nj >> 1][3] : rbl[nj >> 1][2];
                    mma16816(acc[mi][nj], ra[mi], b0, b1);
                }
            // term 3: Al * Bh (reuse ra regs)
#pragma unroll
            for (int mi = 0; mi < 4; mi++) {
                int row = wm + mi * 16 + lrow;
                ldsm4(ra[mi], sAl + SWZ((uint32_t)(row * BKB + kb)));
            }
#pragma unroll
            for (int mi = 0; mi < 4; mi++)
#pragma unroll
                for (int nj = 0; nj < 4; nj++) {
                    uint32_t b0 = (nj & 1) ? rbh[nj >> 1][1] : rbh[nj >> 1][0];
                    uint32_t b1 = (nj & 1) ? rbh[nj >> 1][3] : rbh[nj >> 1][2];
                    mma16816(acc[mi][nj], ra[mi], b0, b1);
                }
        }
        __syncthreads();
    }

    // epilogue
    const int er = lane >> 2;            // 0..7
    const int ec = (lane & 3) * 2;
#pragma unroll
    for (int mi = 0; mi < 4; mi++) {
#pragma unroll
        for (int nj = 0; nj < 4; nj++) {
            int col = n0 + wn + nj * 8 + ec;
            int row0 = m0 + wm + mi * 16 + er;
            int row1 = row0 + 8;
            float* p0 = C + (size_t)row0 * N + col;
            float* p1 = C + (size_t)row1 * N + col;
            float2 v0 = make_float2(acc[mi][nj][0], acc[mi][nj][1]);
            float2 v1 = make_float2(acc[mi][nj][2], acc[mi][nj][3]);
            *(float2*)p0 = v0;
            *(float2*)p1 = v1;
            if (Chi) {
                uint16_t h0, l0, h1, l1;
                split1(v0.x, h0, l0); split1(v0.y, h1, l1);
                uint32_t hp = (uint32_t)h0 | ((uint32_t)h1 << 16);
                uint32_t lp = (uint32_t)l0 | ((uint32_t)l1 << 16);
                size_t o0 = ((size_t)row0 * N + col) >> 1;
                ((uint32_t*)Chi)[o0] = hp;
                ((uint32_t*)Clo)[o0] = lp;
                split1(v1.x, h0, l0); split1(v1.y, h1, l1);
                hp = (uint32_t)h0 | ((uint32_t)h1 << 16);
                lp = (uint32_t)l0 | ((uint32_t)l1 << 16);
                size_t o1 = ((size_t)row1 * N + col) >> 1;
                ((uint32_t*)Chi)[o1] = hp;
                ((uint32_t*)Clo)[o1] = lp;
            }
        }
    }
}

// =========================== recurrence =====================================
__device__ __forceinline__ float fast_tanh(float x) {
    float y;
    asm("tanh.approx.f32 %0, %1;" : "=f"(y) : "f"(x));
    return y;
}

#define RGRP 8
__global__ __launch_bounds__(64) void recurrence_kernel(
    const float* __restrict__ xw, const float* __restrict__ xp,
    const float* __restrict__ h0, const float* __restrict__ alpha_raw,
    const float* __restrict__ bias, const float* __restrict__ bgate,
    __nv_bfloat16* __restrict__ chi, __nv_bfloat16* __restrict__ clo,
    float* __restrict__ hfin, int B, int T, int D) {
    int idx = blockIdx.x * blockDim.x + threadIdx.x;
    if (idx >= B * D) return;
    int bb = idx / D;
    int d  = idx - bb * D;

    float alpha = 1.f / (1.f + __expf(-alpha_raw[d]));
    float bv = bias[d];
    float bg = bgate[d];
    float h  = h0[idx];

    size_t base = (size_t)bb * T * D + d;

    float bw[2][RGRP], bp[2][RGRP];
#pragma unroll
    for (int i = 0; i < RGRP; i++) {
        size_t o = base + (size_t)i * D;
        bw[0][i] = xw[o]; bp[0][i] = xp[o];
    }
    const int NG = T / RGRP;
    for (int g = 0; g < NG; g++) {
        int cur = g & 1;
        if (g + 1 < NG) {
#pragma unroll
            for (int i = 0; i < RGRP; i++) {
                size_t o = base + (size_t)((g + 1) * RGRP + i) * D;
                bw[cur ^ 1][i] = xw[o]; bp[cur ^ 1][i] = xp[o];
            }
        }
#pragma unroll
        for (int i = 0; i < RGRP; i++) {
            float pre = fmaf(alpha, h, bw[cur][i] + bv);
            h = fast_tanh(pre);
            float gt = bp[cur][i] + bg;
            float sg = 1.f / (1.f + __expf(-gt));
            float o = h * (gt * sg);
            uint16_t hi, lo;
            split1(o, hi, lo);
            size_t off = base + (size_t)(g * RGRP + i) * D;
            ((uint16_t*)chi)[off] = hi;
            ((uint16_t*)clo)[off] = lo;
        }
    }
    if (hfin) hfin[idx] = h;
}

// ============================== launch ======================================
extern "C" void kernel_launch(void* const* d_in, const int* in_sizes, int n_in,
                              void* d_out, int out_size) {
    const float* x         = (const float*)d_in[0];
    const float* h0        = (const float*)d_in[1];
    const float* W_in      = (const float*)d_in[2];
    const float* W_x       = (const float*)d_in[3];
    const float* alpha_raw = (const float*)d_in[4];
    const float* b         = (const float*)d_in[5];
    const float* b_gate    = (const float*)d_in[6];
    const float* W_out     = (const float*)d_in[7];
    float* out = (float*)d_out;

    const int D   = in_sizes[4];          // 1024
    const int BD  = in_sizes[1];          // B*D
    const int Bn  = BD / D;               // 8
    const int BTD = in_sizes[0];          // B*T*D
    const int T   = BTD / BD;             // 2048
    const int M   = Bn * T;               // 16384

    float *xproj, *xw, *dummyf;
    __nv_bfloat16 *xh, *xl, *xph, *xpl, *ch, *cl;
    __nv_bfloat16 *wih, *wil, *wxh, *wxl, *woh, *wol;
    cudaGetSymbolAddress((void**)&xproj, g_xproj);
    cudaGetSymbolAddress((void**)&xw, g_xw);
    cudaGetSymbolAddress((void**)&xh, g_xh);
    cudaGetSymbolAddress((void**)&xl, g_xl);
    cudaGetSymbolAddress((void**)&xph, g_xph);
    cudaGetSymbolAddress((void**)&xpl, g_xpl);
    cudaGetSymbolAddress((void**)&ch, g_ch);
    cudaGetSymbolAddress((void**)&cl, g_cl);
    cudaGetSymbolAddress((void**)&wih, g_wih);
    cudaGetSymbolAddress((void**)&wil, g_wil);
    cudaGetSymbolAddress((void**)&wxh, g_wxh);
    cudaGetSymbolAddress((void**)&wxl, g_wxl);
    cudaGetSymbolAddress((void**)&woh, g_woh);
    cudaGetSymbolAddress((void**)&wol, g_wol);
    (void)dummyf;

    cudaFuncSetAttribute(gemm_bf16x3, cudaFuncAttributeMaxDynamicSharedMemorySize, GSMEM);

    // splits
    {
        int n4 = BTD / 4;
        split_kernel<<<(n4 + 255) / 256, 256>>>(x, xh, xl, n4);
        int w4 = (D * D) / 4;
        split_kernel<<<(w4 + 255) / 256, 256>>>(W_in, wih, wil, w4);
        split_kernel<<<(w4 + 255) / 256, 256>>>(W_x, wxh, wxl, w4);
        split_kernel<<<(w4 + 255) / 256, 256>>>(W_out, woh, wol, w4);
    }

    dim3 blk(256);
    dim3 grid(D / 128, M / 128);          // (8, 128)

    // 1) x_proj = x @ W_in^T  (fp32 + hi/lo split fused in epilogue)
    gemm_bf16x3<<<grid, blk, GSMEM>>>(xh, xl, wih, wil, xproj, xph, xpl, M, D, D);
    // 2) xw = x_proj @ W_x^T
    gemm_bf16x3<<<grid, blk, GSMEM>>>(xph, xpl, wxh, wxl, xw, nullptr, nullptr, M, D, D);

    // 3) recurrence -> cell hi/lo, h_final
    float* hfin = (out_size >= BTD + BD) ? (out + BTD) : nullptr;
    int nthreads = Bn * D;
    recurrence_kernel<<<(nthreads + 63) / 64, 64>>>(
        xw, xproj, h0, alpha_raw, b, b_gate, ch, cl, hfin, Bn, T, D);

    // 4) output = cell_out @ W_out^T
    gemm_bf16x3<<<grid, blk, GSMEM>>>(ch, cl, woh, wol, out, nullptr, nullptr, M, D, D);
}